// round 15
// baseline (speedup 1.0000x reference)
#include <cuda_runtime.h>

#define BB 256
#define NN 192
#define CC 256
#define GG 8
#define DD 32

// softmax via exp2: fold SCALE * log2(e) into q
#define CSCALE (0.17677669529663688f * 1.4426950408889634f)

typedef unsigned long long u64;

// scratch (allocation-free rule: __device__ global)
// g_q[b][n][o] = CSCALE * (x_n Wq^T + bq)[o]   (6 MB)
__device__ float g_q[BB * NN * DD];

// ---------- packed f32x2 helpers (sm_100+) ----------
__device__ __forceinline__ u64 pack2(float x, float y) {
    u64 r; asm("mov.b64 %0,{%1,%2};" : "=l"(r) : "f"(x), "f"(y)); return r;
}
__device__ __forceinline__ void unpack2(u64 v, float& x, float& y) {
    asm("mov.b64 {%0,%1},%2;" : "=f"(x), "=f"(y) : "l"(v));
}
__device__ __forceinline__ void ffma2(u64& d, u64 a, u64 b) {
    asm("fma.rn.f32x2 %0,%1,%2,%0;" : "+l"(d) : "l"(a), "l"(b));
}
__device__ __forceinline__ float ex2(float x) {
    float r; asm("ex2.approx.ftz.f32 %0,%1;" : "=f"(r) : "f"(x)); return r;
}

// ============================================================
// proj_q: q = (x Wq^T + bq) * CSCALE  (measured good, unchanged).
// 32 rows/block, 128 threads, 64KB smem, occ 3.
// bk is provably irrelevant (constant-in-j logit shift, cancels in softmax).
// ============================================================
__global__ void __launch_bounds__(128, 3) proj_q_kernel(
    const float* __restrict__ x, const float* __restrict__ Wq,
    const float* __restrict__ bq)
{
    extern __shared__ u64 smq[];
    u64* xs2 = smq;            // [32][128] u64 = 32KB
    u64* Wt2 = smq + 4096;     // [128][32] u64 = 32KB

    const int tid = threadIdx.x;
    const int w = tid >> 5, lane = tid & 31;
    const long row0 = (long)blockIdx.x * 32;

    for (int idx = tid; idx < DD * CC; idx += 128) {
        int d = idx >> 8, c = idx & 255;
        ((float*)&Wt2[(c >> 1) * 32 + d])[c & 1] = Wq[idx];
    }
    {
        const float4* src = (const float4*)(x + row0 * CC);
        float4* dst = (float4*)xs2;
#pragma unroll
        for (int t = 0; t < 16; ++t) dst[tid + t * 128] = src[tid + t * 128];
    }
    __syncthreads();

    u64 acc[8];
#pragma unroll
    for (int r = 0; r < 8; ++r) acc[r] = 0ull;
    const u64* xbase = xs2 + (w * 8) * 128;
#pragma unroll 4
    for (int c2 = 0; c2 < 128; ++c2) {
        u64 w2 = Wt2[c2 * 32 + lane];
#pragma unroll
        for (int r = 0; r < 8; ++r)
            ffma2(acc[r], xbase[r * 128 + c2], w2);
    }
    const float bias = bq[lane];
#pragma unroll
    for (int r = 0; r < 8; ++r) {
        float lo, hi; unpack2(acc[r], lo, hi);
        g_q[(row0 + w * 8 + r) * DD + lane] = (lo + hi + bias) * CSCALE;
    }
}

// ============================================================
// attn: R14 structure; only P3 retiled (6i x 4d x j-split-2).
// 1 block per (b,g,i-half of 96); 256 threads; 114,176B smem; occ 2.
//   q_s [96][36]  @ 0     (3456 floats)  qt rows; P3: partial scratch
//   vT  [32][196] @ 3456  (6272 floats)  x group slice transposed [d][j]
//   ST  [96][196] @ 9728  (18816 floats) P0: rawq[96][36]+Wk2[512]; P1+: p
// ============================================================
#define OFF_VT  3456
#define OFF_ST  9728
#define SM_FLOATS 28544

__global__ void __launch_bounds__(256, 2) attn_kernel(
    const float* __restrict__ x, const float* __restrict__ Wk,
    float* __restrict__ ctx_out, float* __restrict__ attn_out)
{
    extern __shared__ float sm[];
    float* q_s  = sm;
    float* vT   = sm + OFF_VT;
    float* ST   = sm + OFF_ST;
    float* rawq = ST;                     // [96][36], P0 only (dead after P0b)
    u64*   Wk2  = (u64*)(ST + 3456);      // [512] = Wk[g] rows as u64 pairs

    const int tid = threadIdx.x;
    const int bg = blockIdx.x >> 1;        // b*8+g
    const int b = bg >> 3, g = bg & 7;
    const int i0 = (blockIdx.x & 1) * 96;

    // ---------------- P0: stage rawq, Wk2, vT ----------------------------
#pragma unroll
    for (int t = 0; t < 3; ++t) {          // 96 rows x 8 float4 = 768
        int idx = tid + t * 256;
        int i = idx >> 3, f = idx & 7;
        ((float4*)(rawq + i * 36))[f] =
            ((const float4*)(g_q + ((size_t)(b * NN) + i0 + i) * DD))[f];
    }
    {   // Wk[g]: row-major [o][i2]; u64 copy -> Wk2[o*16+p] = (Wk[o][2p], Wk[o][2p+1])
        const u64* wksrc = (const u64*)(Wk + g * DD * DD);
        for (int idx = tid; idx < 512; idx += 256) Wk2[idx] = wksrc[idx];
    }
#pragma unroll
    for (int t = 0; t < 6; ++t) {          // 1536 float4, transpose scatter
        int idx = tid + t * 256;
        int n = idx >> 3, f = idx & 7;
        float4 v4 = ((const float4*)(x + ((size_t)(b * NN) + n) * CC + g * DD))[f];
        vT[(4 * f    ) * 196 + n] = v4.x;
        vT[(4 * f + 1) * 196 + n] = v4.y;
        vT[(4 * f + 2) * 196 + n] = v4.z;
        vT[(4 * f + 3) * 196 + n] = v4.w;
    }
    __syncthreads();

    // ---------------- P0b: qt[i][i2] = sum_o rawq[i][o] * Wk[g][o][i2] ---
    // threads 0..191: iqt = tid>>1 (row), half = tid&1 -> i2-pairs 8h..8h+7
    if (tid < 192) {
        const int iqt = tid >> 1, half = tid & 1;
        u64 qacc[8];
#pragma unroll
        for (int p = 0; p < 8; ++p) qacc[p] = 0ull;
        const float* qr = rawq + iqt * 36;
#pragma unroll 8
        for (int o = 0; o < 32; ++o) {
            float qv = qr[o];              // 2-lane broadcast
            u64 qq = pack2(qv, qv);
            const u64* wrow = Wk2 + o * 16 + 8 * half;
#pragma unroll
            for (int p = 0; p < 8; ++p)
                ffma2(qacc[p], qq, wrow[p]);
        }
        u64* qdst = (u64*)(q_s + iqt * 36);   // 36 floats = 18 u64 stride
#pragma unroll
        for (int p = 0; p < 8; ++p) qdst[8 * half + p] = qacc[p];
    }
    __syncthreads();

    // ---------------- P1: S + fused softmax + p/attn write ---------------
    // jq = tid&15 -> j block [12jq, 12jq+12); iq = tid>>4 -> i = iq+16m, m<6
    // No max subtraction: |S_log2| <~ 13, exp2 safe in fp32; softmax is
    // shift-invariant so the result is identical.
    {
        const int jq = tid & 15, iq = tid >> 4;
        u64 acc[36];
#pragma unroll
        for (int t = 0; t < 36; ++t) acc[t] = 0ull;

#pragma unroll 1
        for (int d2 = 0; d2 < 16; ++d2) {
            const int d0 = 2 * d2;
            u64 qp[6];
#pragma unroll
            for (int m = 0; m < 6; ++m)
                qp[m] = *(const u64*)(q_s + (iq + 16 * m) * 36 + d0);  // (d0,d0+1)
            {   // v row d0
                const float4* vr = (const float4*)(vT + d0 * 196);
                u64 vv[6];
#pragma unroll
                for (int c = 0; c < 3; ++c) {
                    float4 v4 = vr[3 * jq + c];
                    vv[2 * c]     = pack2(v4.x, v4.y);
                    vv[2 * c + 1] = pack2(v4.z, v4.w);
                }
#pragma unroll
                for (int m = 0; m < 6; ++m) {
                    float ql, qh; unpack2(qp[m], ql, qh); (void)qh;
                    u64 qa = pack2(ql, ql);
#pragma unroll
                    for (int n = 0; n < 6; ++n)
                        ffma2(acc[m * 6 + n], qa, vv[n]);
                }
            }
            {   // v row d0+1
                const float4* vr = (const float4*)(vT + (d0 + 1) * 196);
                u64 vv[6];
#pragma unroll
                for (int c = 0; c < 3; ++c) {
                    float4 v4 = vr[3 * jq + c];
                    vv[2 * c]     = pack2(v4.x, v4.y);
                    vv[2 * c + 1] = pack2(v4.z, v4.w);
                }
#pragma unroll
                for (int m = 0; m < 6; ++m) {
                    float ql, qh; unpack2(qp[m], ql, qh); (void)ql;
                    u64 qb = pack2(qh, qh);
#pragma unroll
                    for (int n = 0; n < 6; ++n)
                        ffma2(acc[m * 6 + n], qb, vv[n]);
                }
            }
        }

        // ---- fused softmax epilogue (registers + half-warp shfl) ----
        float e[72];
#pragma unroll
        for (int t = 0; t < 36; ++t) {
            float lo, hi; unpack2(acc[t], lo, hi);
            e[2 * t]     = ex2(lo);
            e[2 * t + 1] = ex2(hi);
        }
        float inv[6];
#pragma unroll
        for (int m = 0; m < 6; ++m) {
            float s = 0.f;
#pragma unroll
            for (int jj = 0; jj < 12; ++jj) s += e[m * 12 + jj];
            // 16 lanes sharing iq are a contiguous half-warp covering all j
#pragma unroll
            for (int o = 1; o < 16; o <<= 1)
                s += __shfl_xor_sync(0xffffffffu, s, o);
            inv[m] = 1.0f / s;
        }
        // normalized p to ST (for P3) and attn gmem, straight from registers
#pragma unroll
        for (int m = 0; m < 6; ++m) {
            const int i = iq + 16 * m;
            float4* srow = (float4*)(ST + i * 196);
            float4 p4[3];
#pragma unroll
            for (int c = 0; c < 3; ++c) {
                p4[c] = make_float4(e[m * 12 + 4 * c    ] * inv[m],
                                    e[m * 12 + 4 * c + 1] * inv[m],
                                    e[m * 12 + 4 * c + 2] * inv[m],
                                    e[m * 12 + 4 * c + 3] * inv[m]);
                srow[3 * jq + c] = p4[c];
            }
            if (attn_out) {
                float4* adst = (float4*)(attn_out +
                    ((size_t)bg * NN + i0 + i) * NN + 12 * jq);
#pragma unroll
                for (int c = 0; c < 3; ++c) adst[c] = p4[c];
            }
        }
    }
    __syncthreads();

    // ---------------- P3: ctx[i][d] = sum_j p[i][j] * v[j][d] ------------
    // dg = tid&7 -> d = 4dg+dd (dd<4); ih = (tid>>3)&15 -> i = 6ih+a (a<6);
    // jh = tid>>7 -> j-half (24 float4 steps each). e-loads amortize over
    // 4 d, v-loads over 6 i. Halves combined via scratch in dead q_s.
    if (ctx_out) {
        const int dg = tid & 7, ih = (tid >> 3) & 15, jh = tid >> 7;
        u64 acc[24];
#pragma unroll
        for (int t = 0; t < 24; ++t) acc[t] = 0ull;

        const int cbase = 24 * jh;
#pragma unroll 2
        for (int cc = 0; cc < 24; ++cc) {           // 4 j per step
            const int c = cbase + cc;
            u64 v2[8];
#pragma unroll
            for (int dd = 0; dd < 4; ++dd) {
                float4 v4 = ((const float4*)(vT + (4 * dg + dd) * 196))[c];
                v2[2 * dd]     = pack2(v4.x, v4.y);
                v2[2 * dd + 1] = pack2(v4.z, v4.w);
            }
#pragma unroll
            for (int a = 0; a < 6; ++a) {
                float4 e4 = ((const float4*)(ST + (6 * ih + a) * 196))[c];  // broadcast
                u64 e0 = pack2(e4.x, e4.y), e1 = pack2(e4.z, e4.w);
#pragma unroll
                for (int dd = 0; dd < 4; ++dd) {
                    ffma2(acc[a * 4 + dd], e0, v2[2 * dd]);
                    ffma2(acc[a * 4 + dd], e1, v2[2 * dd + 1]);
                }
            }
        }
        // reduce j-pairs -> per-thread partials
        float part[24];
#pragma unroll
        for (int t = 0; t < 24; ++t) {
            float lo, hi; unpack2(acc[t], lo, hi);
            part[t] = lo + hi;
        }
        float4* scratch4 = (float4*)q_s;            // 6*128 float4 = 12,288B
        if (jh == 1) {
#pragma unroll
            for (int a = 0; a < 6; ++a)
                scratch4[a * 128 + (tid - 128)] =
                    make_float4(part[a * 4], part[a * 4 + 1],
                                part[a * 4 + 2], part[a * 4 + 3]);
        }
        __syncthreads();
        if (jh == 0) {
#pragma unroll
            for (int a = 0; a < 6; ++a) {
                float4 o = scratch4[a * 128 + tid];
                o.x += part[a * 4];     o.y += part[a * 4 + 1];
                o.z += part[a * 4 + 2]; o.w += part[a * 4 + 3];
                const size_t row = (size_t)(b * NN) + i0 + 6 * ih + a;
                *(float4*)(ctx_out + row * CC + g * DD + 4 * dg) = o;
            }
        }
    }
}

extern "C" void kernel_launch(void* const* d_in, const int* in_sizes, int n_in,
                              void* d_out, int out_size)
{
    const float* x  = (const float*)d_in[0];
    const float* Wq = (const float*)d_in[1];
    const float* bq = (const float*)d_in[2];
    const float* Wk = (const float*)d_in[3];
    // d_in[4] = bk: provably no effect on outputs (cancels in softmax)

    const size_t ctx_elems  = (size_t)BB * NN * CC;          // 12,582,912
    const size_t attn_elems = (size_t)BB * GG * NN * NN;     // 75,497,472

    float* ctx_ptr  = nullptr;
    float* attn_ptr = nullptr;
    const size_t osz = (size_t)out_size;
    if (osz >= ctx_elems + attn_elems) {          // tuple flattened: ctx then attn
        ctx_ptr  = (float*)d_out;
        attn_ptr = (float*)d_out + ctx_elems;
    } else if (osz == attn_elems) {               // attn only
        attn_ptr = (float*)d_out;
    } else {                                      // ctx only
        ctx_ptr = (float*)d_out;
    }

    constexpr int SMEM_P = 64 * 1024;             // proj: 65536 -> occ 3
    constexpr int SMEM_A = SM_FLOATS * 4;         // attn: 114176 -> occ 2
    cudaFuncSetAttribute(proj_q_kernel, cudaFuncAttributeMaxDynamicSharedMemorySize, SMEM_P);
    cudaFuncSetAttribute(attn_kernel,   cudaFuncAttributeMaxDynamicSharedMemorySize, SMEM_A);

    proj_q_kernel<<<BB * NN / 32, 128, SMEM_P>>>(x, Wq, bq);
    attn_kernel<<<BB * GG * 2, 256, SMEM_A>>>(x, Wk, ctx_ptr, attn_ptr);
}